// round 1
// baseline (speedup 1.0000x reference)
#include <cuda_runtime.h>
#include <math.h>

#define NTOK 512
#define NH   12
#define NCH  16
#define NPQ  4
#define NPV  8
#define NCS  384
#define NCZ  128
#define NHC  192          // NH*NCH
#define NOUTD 2112        // NH*(NCZ+NCH+NPV*4)
#define NNN  (NTOK*NTOK)

// ---------------- scratch (static device globals; no runtime allocation) ----
__device__ float g_qraw[NTOK*NHC];              // s@Wq              [i][h*16+c]
__device__ float g_kvraw[NTOK*2*NHC];           // s@Wkv             [i][h*32+c]
__device__ float g_qpraw[NTOK*NH*NPQ*3];        // raw q point proj  [i][d*48+m]
__device__ float g_kvpraw[NTOK*NH*(NPQ+NPV)*3]; // raw kv point proj [i][d*144+m]
__device__ float g_qpts[NTOK*NH*NPQ*3];         // rotated q pts     [i][h][p][d]
__device__ float g_kpts[NTOK*NH*NPQ*3];         // rotated k pts
__device__ float g_vpts[NTOK*NH*NPV*3];         // rotated v pts
__device__ float g_attn[NH*NNN];                // softmaxed attention [h][i][j]
__device__ float g_cat[NTOK*NOUTD];             // concat features

// ---------------- Kernel A: all four projections from s ---------------------
// grid (32, 19), block 256. Block = 16 tokens x 64 columns of one of the 4 W's.
__global__ void proj_kernel(const float* __restrict__ s,
                            const float* __restrict__ Wq,   const float* __restrict__ bq,
                            const float* __restrict__ Wkv,  const float* __restrict__ bkv,
                            const float* __restrict__ Wqp,  const float* __restrict__ bqp,
                            const float* __restrict__ Wkvp, const float* __restrict__ bkvp)
{
    __shared__ float s_s[16][384];
    const int tid = threadIdx.x;
    const int i0  = blockIdx.x * 16;
    for (int idx = tid; idx < 16*384; idx += 256)
        s_s[idx/384][idx%384] = s[i0*384 + idx];
    __syncthreads();

    const float* W; const float* bias; float* out; int Nc; int ct;
    const int by = blockIdx.y;
    if      (by < 3)  { W=Wq;   bias=bq;   out=g_qraw;   Nc=192; ct=by;    }
    else if (by < 9)  { W=Wkv;  bias=bkv;  out=g_kvraw;  Nc=384; ct=by-3;  }
    else if (by < 12) { W=Wqp;  bias=bqp;  out=g_qpraw;  Nc=144; ct=by-9;  }
    else              { W=Wkvp; bias=bkvp; out=g_kvpraw; Nc=432; ct=by-12; }

    const int col = ct*64 + (tid & 63);
    if (col >= Nc) return;
    const int t0 = (tid >> 6) * 4;

    float a0=0.f, a1=0.f, a2=0.f, a3=0.f;
    for (int k = 0; k < 384; k += 4) {
        float w0 = W[(k+0)*Nc + col];
        float w1 = W[(k+1)*Nc + col];
        float w2 = W[(k+2)*Nc + col];
        float w3 = W[(k+3)*Nc + col];
        float4 v;
        v = *(const float4*)&s_s[t0+0][k]; a0 += v.x*w0 + v.y*w1 + v.z*w2 + v.w*w3;
        v = *(const float4*)&s_s[t0+1][k]; a1 += v.x*w0 + v.y*w1 + v.z*w2 + v.w*w3;
        v = *(const float4*)&s_s[t0+2][k]; a2 += v.x*w0 + v.y*w1 + v.z*w2 + v.w*w3;
        v = *(const float4*)&s_s[t0+3][k]; a3 += v.x*w0 + v.y*w1 + v.z*w2 + v.w*w3;
    }
    const float bv = bias[col];
    out[(i0+t0+0)*Nc + col] = a0 + bv;
    out[(i0+t0+1)*Nc + col] = a1 + bv;
    out[(i0+t0+2)*Nc + col] = a2 + bv;
    out[(i0+t0+3)*Nc + col] = a3 + bv;
}

// ---------------- Kernel B: apply rotation+translation to points -----------
__global__ void rotpts_kernel(const float* __restrict__ rot, const float* __restrict__ trans)
{
    const int gid = blockIdx.x*256 + threadIdx.x;
    if (gid >= NTOK*192) return;
    const int i = gid / 192, m = gid % 192;
    const float* R = rot + i*9;
    const float tx = trans[i*3+0], ty = trans[i*3+1], tz = trans[i*3+2];
    float x, y, zc; float* dst;
    if (m < 48) {
        const float* src = g_qpraw + i*144;
        x = src[m]; y = src[48+m]; zc = src[96+m];
        dst = g_qpts + i*144 + m*3;
    } else {
        const int mm = m - 48;
        const float* src = g_kvpraw + i*432;
        x = src[mm]; y = src[144+mm]; zc = src[288+mm];
        const int h = mm / 12, pp = mm % 12;
        if (pp < 4) dst = g_kpts + i*144 + (h*4+pp)*3;
        else        dst = g_vpts + i*288 + (h*8 + pp-4)*3;
    }
    dst[0] = R[0]*x + R[1]*y + R[2]*zc + tx;
    dst[1] = R[3]*x + R[4]*y + R[5]*zc + ty;
    dst[2] = R[6]*x + R[7]*y + R[8]*zc + tz;
}

// ---------------- Kernel C: fused logits (z@Wb + q.k + pt term) + softmax ---
// grid 512 (one per query i), block 512 (one thread per key j).
__global__ void attn_kernel(const float* __restrict__ z,
                            const float* __restrict__ Wb, const float* __restrict__ bb,
                            const float* __restrict__ hwts, const float* __restrict__ mask)
{
    __shared__ float wbT[NH*NCZ];   // Wb transposed [h][c]
    __shared__ float qs[NHC];
    __shared__ float qps[NH*NPQ*3];
    __shared__ float sbb[NH];
    __shared__ float shw[NH];
    __shared__ float s_red[16];
    __shared__ float s_val;

    const int i = blockIdx.x;
    const int tid = threadIdx.x;
    const int j = tid;

    for (int idx = tid; idx < NH*NCZ; idx += 512) {
        const int h = idx >> 7, c = idx & 127;
        wbT[idx] = Wb[c*NH + h];
    }
    if (tid < NHC) qs[tid] = g_qraw[i*NHC + tid];
    else if (tid < NHC + 144) qps[tid-NHC] = g_qpts[i*144 + (tid-NHC)];
    else if (tid < NHC + 144 + NH) {
        const int h = tid - (NHC+144);
        sbb[h] = bb[h];
        shw[h] = log1pf(__expf(hwts[h])) * 0.1360827635f;   // softplus * sqrt(1/54)
    }
    __syncthreads();

    float lg[NH];
    #pragma unroll
    for (int h = 0; h < NH; h++) lg[h] = 0.f;

    // b_pair: z[i,j,:] . Wb[:,h]
    const float4* zr = (const float4*)(z + (size_t)(i*NTOK + j) * NCZ);
    for (int cg = 0; cg < 32; cg++) {
        const float4 zv = zr[cg];
        #pragma unroll
        for (int h = 0; h < NH; h++) {
            const float4 wv = *(const float4*)&wbT[h*NCZ + cg*4];
            lg[h] += zv.x*wv.x + zv.y*wv.y + zv.z*wv.z + zv.w*wv.w;
        }
    }

    const float mterm = 100000.0f * (mask[i]*mask[j] - 1.0f);
    const float sc_qk = 0.1443375673f;   // sqrt(1/(3*CH))
    #pragma unroll
    for (int h = 0; h < NH; h++) {
        const float4* kr = (const float4*)(g_kvraw + j*384 + h*32);
        const float4* qr = (const float4*)(qs + h*16);
        float dot = 0.f;
        #pragma unroll
        for (int u = 0; u < 4; u++) {
            const float4 kv = kr[u], qv = qr[u];
            dot += kv.x*qv.x + kv.y*qv.y + kv.z*qv.z + kv.w*qv.w;
        }
        const float4* kpr = (const float4*)(g_kpts + j*144 + h*12);
        const float* qp = qps + h*12;
        const float4 k0 = kpr[0], k1 = kpr[1], k2 = kpr[2];
        float d, dd = 0.f;
        d = qp[0] - k0.x; dd += d*d;
        d = qp[1] - k0.y; dd += d*d;
        d = qp[2] - k0.z; dd += d*d;
        d = qp[3] - k0.w; dd += d*d;
        d = qp[4] - k1.x; dd += d*d;
        d = qp[5] - k1.y; dd += d*d;
        d = qp[6] - k1.z; dd += d*d;
        d = qp[7] - k1.w; dd += d*d;
        d = qp[8] - k2.x; dd += d*d;
        d = qp[9] - k2.y; dd += d*d;
        d = qp[10] - k2.z; dd += d*d;
        d = qp[11] - k2.w; dd += d*d;
        lg[h] = 0.5773502692f*(lg[h] + sbb[h]) + sc_qk*dot - 0.5f*shw[h]*dd + mterm;
    }

    // 12 per-head softmaxes across the block (512 keys)
    const int lane = tid & 31, wrp = tid >> 5;
    #pragma unroll 1
    for (int h = 0; h < NH; h++) {
        __syncthreads();
        const float v = lg[h];
        float m = v;
        #pragma unroll
        for (int o = 16; o > 0; o >>= 1) m = fmaxf(m, __shfl_xor_sync(0xffffffffu, m, o));
        if (lane == 0) s_red[wrp] = m;
        __syncthreads();
        if (tid == 0) {
            float mm = -3.0e38f;
            for (int ww = 0; ww < 16; ww++) mm = fmaxf(mm, s_red[ww]);
            s_val = mm;
        }
        __syncthreads();
        const float e = __expf(v - s_val);
        __syncthreads();
        float su = e;
        #pragma unroll
        for (int o = 16; o > 0; o >>= 1) su += __shfl_xor_sync(0xffffffffu, su, o);
        if (lane == 0) s_red[wrp] = su;
        __syncthreads();
        if (tid == 0) {
            float t = 0.f;
            for (int ww = 0; ww < 16; ww++) t += s_red[ww];
            s_val = t;
        }
        __syncthreads();
        g_attn[h*NNN + i*NTOK + j] = e * (1.0f / s_val);
    }
}

// ---------------- Kernel D: o, o_pt (+inv rot, norms), o_pair --------------
// grid 512 (one per i), block 256.
__global__ void out_kernel(const float* __restrict__ z,
                           const float* __restrict__ rot, const float* __restrict__ trans)
{
    __shared__ float a_s[NH*NTOK];   // 6144 floats (24 KB)
    __shared__ float p_s[6144];      // partials / o_pt scratch (24 KB)
    const int i = blockIdx.x;
    const int tid = threadIdx.x;

    for (int idx = tid; idx < NH*NTOK; idx += 256)
        a_s[idx] = g_attn[(idx >> 9)*NNN + i*NTOK + (idx & 511)];
    __syncthreads();

    // o = a@v   and   o_pt = a@v_pts (accumulated in global frame)
    if (tid < 48) {
        const int h = tid >> 2, cg = tid & 3;
        float4 acc = make_float4(0.f,0.f,0.f,0.f);
        const float* base = g_kvraw + h*32 + 16 + cg*4;
        const float* ah = a_s + h*NTOK;
        for (int jj = 0; jj < NTOK; jj++) {
            const float4 vv = *(const float4*)(base + jj*384);
            const float a = ah[jj];
            acc.x += a*vv.x; acc.y += a*vv.y; acc.z += a*vv.z; acc.w += a*vv.w;
        }
        *(float4*)&g_cat[i*NOUTD + h*16 + cg*4] = acc;
    } else if (tid < 120) {
        const int m = tid - 48;
        const int h = m / 6, g = m % 6;
        float4 acc = make_float4(0.f,0.f,0.f,0.f);
        const float* base = g_vpts + h*24 + g*4;
        const float* ah = a_s + h*NTOK;
        for (int jj = 0; jj < NTOK; jj++) {
            const float4 vv = *(const float4*)(base + jj*288);
            const float a = ah[jj];
            acc.x += a*vv.x; acc.y += a*vv.y; acc.z += a*vv.z; acc.w += a*vv.w;
        }
        *(float4*)&p_s[h*24 + g*4] = acc;
    }
    __syncthreads();

    // inverse rotation, norms
    if (tid < 96) {
        const int h = tid >> 3, p = tid & 7;
        const int m = h*8 + p;
        const float gx = p_s[m*3+0] - trans[i*3+0];
        const float gy = p_s[m*3+1] - trans[i*3+1];
        const float gz = p_s[m*3+2] - trans[i*3+2];
        const float* R = rot + i*9;
        const float lx = R[0]*gx + R[3]*gy + R[6]*gz;
        const float ly = R[1]*gx + R[4]*gy + R[7]*gz;
        const float lz = R[2]*gx + R[5]*gy + R[8]*gz;
        g_cat[i*NOUTD + 192 + m] = lx;
        g_cat[i*NOUTD + 288 + m] = ly;
        g_cat[i*NOUTD + 384 + m] = lz;
        g_cat[i*NOUTD + 480 + m] = sqrtf(lx*lx + ly*ly + lz*lz + 1e-8f);
    }
    __syncthreads();

    // o_pair = a @ z : warp w covers j-quarter (w&3), heads (w>>2)*6..+5.
    const int w = tid >> 5, l = tid & 31;
    const int jq = w & 3;
    const int hbase = (w >> 2) * 6;
    float4 acc[6];
    #pragma unroll
    for (int hh = 0; hh < 6; hh++) acc[hh] = make_float4(0.f,0.f,0.f,0.f);
    for (int jj = 0; jj < 128; jj++) {
        const int j = jq*128 + jj;
        const float4 zv = ((const float4*)(z + (size_t)(i*NTOK + j)*NCZ))[l];
        #pragma unroll
        for (int hh = 0; hh < 6; hh++) {
            const float a = a_s[(hbase+hh)*NTOK + j];
            acc[hh].x += a*zv.x; acc[hh].y += a*zv.y; acc[hh].z += a*zv.z; acc[hh].w += a*zv.w;
        }
    }
    #pragma unroll
    for (int hh = 0; hh < 6; hh++)
        *(float4*)&p_s[w*768 + hh*128 + l*4] = acc[hh];
    __syncthreads();

    for (int o = tid; o < 1536; o += 256) {
        const int h = o >> 7, c = o & 127;
        float sv = 0.f;
        if (h < 6) { for (int ww = 0; ww < 4; ww++) sv += p_s[ww*768 + h*128 + c]; }
        else       { for (int ww = 4; ww < 8; ww++) sv += p_s[ww*768 + (h-6)*128 + c]; }
        g_cat[i*NOUTD + 576 + o] = sv;
    }
}

// ---------------- Kernel E: final GEMM cat(512x2112) @ Wout(2112x384) ------
// grid (12,16), block 256, 32x32 tile, 2x2 per thread.
__global__ void final_gemm(const float* __restrict__ Wout, const float* __restrict__ bout,
                           float* __restrict__ out)
{
    __shared__ float As[32][33];
    __shared__ float Bs[32][33];
    const int bx = blockIdx.x, by = blockIdx.y;
    const int tid = threadIdx.x;
    const int tx = tid & 15, ty = tid >> 4;
    float c00=0.f, c01=0.f, c10=0.f, c11=0.f;
    for (int kt = 0; kt < NOUTD; kt += 32) {
        for (int idx = tid; idx < 1024; idx += 256) {
            const int r = idx >> 5, c = idx & 31;
            As[r][c] = g_cat[(by*32 + r)*NOUTD + kt + c];
            Bs[r][c] = Wout[(kt + r)*NCS + bx*32 + c];
        }
        __syncthreads();
        #pragma unroll
        for (int k = 0; k < 32; k++) {
            const float aa0 = As[ty*2+0][k], aa1 = As[ty*2+1][k];
            const float bb0 = Bs[k][tx*2+0], bb1 = Bs[k][tx*2+1];
            c00 += aa0*bb0; c01 += aa0*bb1; c10 += aa1*bb0; c11 += aa1*bb1;
        }
        __syncthreads();
    }
    const int row = by*32 + ty*2, col = bx*32 + tx*2;
    out[row*NCS + col]         = c00 + bout[col];
    out[row*NCS + col+1]       = c01 + bout[col+1];
    out[(row+1)*NCS + col]     = c10 + bout[col];
    out[(row+1)*NCS + col+1]   = c11 + bout[col+1];
}

// ---------------- launch -----------------------------------------------------
extern "C" void kernel_launch(void* const* d_in, const int* in_sizes, int n_in,
                              void* d_out, int out_size)
{
    const float* s     = (const float*)d_in[0];
    const float* z     = (const float*)d_in[1];
    const float* rot   = (const float*)d_in[2];
    const float* trans = (const float*)d_in[3];
    const float* mask  = (const float*)d_in[4];
    const float* Wq    = (const float*)d_in[5];
    const float* bq    = (const float*)d_in[6];
    const float* Wkv   = (const float*)d_in[7];
    const float* bkv   = (const float*)d_in[8];
    const float* Wqp   = (const float*)d_in[9];
    const float* bqp   = (const float*)d_in[10];
    const float* Wkvp  = (const float*)d_in[11];
    const float* bkvp  = (const float*)d_in[12];
    const float* Wb    = (const float*)d_in[13];
    const float* bb    = (const float*)d_in[14];
    const float* hwts  = (const float*)d_in[15];
    const float* Wout  = (const float*)d_in[16];
    const float* bout  = (const float*)d_in[17];
    float* out = (float*)d_out;

    proj_kernel<<<dim3(32,19,1), 256>>>(s, Wq,bq, Wkv,bkv, Wqp,bqp, Wkvp,bkvp);
    rotpts_kernel<<<(NTOK*192 + 255)/256, 256>>>(rot, trans);
    attn_kernel<<<NTOK, 512>>>(z, Wb, bb, hwts, mask);
    out_kernel<<<NTOK, 256>>>(z, rot, trans);
    final_gemm<<<dim3(12,16,1), 256>>>(Wout, bout, out);
}

// round 2
// speedup vs baseline: 1.2265x; 1.2265x over previous
#include <cuda_runtime.h>
#include <math.h>

#define NTOK 512
#define NH   12
#define NCH  16
#define NPQ  4
#define NPV  8
#define NCS  384
#define NCZ  128
#define NHC  192          // NH*NCH
#define NOUTD 2112        // NH*(NCZ+NCH+NPV*4)
#define NNN  (NTOK*NTOK)

// ---------------- scratch (static device globals; no runtime allocation) ----
__device__ float g_qraw[NTOK*NHC];              // s@Wq              [i][h*16+c]
__device__ float g_kvraw[NTOK*2*NHC];           // s@Wkv             [i][h*32+c]
__device__ float g_qpraw[NTOK*NH*NPQ*3];        // raw q point proj  [i][d*48+m]
__device__ float g_kvpraw[NTOK*NH*(NPQ+NPV)*3]; // raw kv point proj [i][d*144+m]
__device__ float g_qpts[NTOK*NH*NPQ*3];         // rotated q pts     [i][h][p][d]
__device__ float g_kpts[NTOK*NH*NPQ*3];         // rotated k pts
__device__ float g_vpts[NTOK*NH*NPV*3];         // rotated v pts
__device__ float g_attn[NH*NNN];                // softmaxed attention [h][i][j]
__device__ float g_cat[NTOK*NOUTD];             // concat features

// ---------------- Kernel A: all four projections from s ---------------------
__global__ void proj_kernel(const float* __restrict__ s,
                            const float* __restrict__ Wq,   const float* __restrict__ bq,
                            const float* __restrict__ Wkv,  const float* __restrict__ bkv,
                            const float* __restrict__ Wqp,  const float* __restrict__ bqp,
                            const float* __restrict__ Wkvp, const float* __restrict__ bkvp)
{
    __shared__ float s_s[16][384];
    const int tid = threadIdx.x;
    const int i0  = blockIdx.x * 16;
    for (int idx = tid; idx < 16*384; idx += 256)
        s_s[idx/384][idx%384] = s[i0*384 + idx];
    __syncthreads();

    const float* W; const float* bias; float* out; int Nc; int ct;
    const int by = blockIdx.y;
    if      (by < 3)  { W=Wq;   bias=bq;   out=g_qraw;   Nc=192; ct=by;    }
    else if (by < 9)  { W=Wkv;  bias=bkv;  out=g_kvraw;  Nc=384; ct=by-3;  }
    else if (by < 12) { W=Wqp;  bias=bqp;  out=g_qpraw;  Nc=144; ct=by-9;  }
    else              { W=Wkvp; bias=bkvp; out=g_kvpraw; Nc=432; ct=by-12; }

    const int col = ct*64 + (tid & 63);
    if (col >= Nc) return;
    const int t0 = (tid >> 6) * 4;

    float a0=0.f, a1=0.f, a2=0.f, a3=0.f;
    #pragma unroll 4
    for (int k = 0; k < 384; k += 4) {
        float w0 = W[(k+0)*Nc + col];
        float w1 = W[(k+1)*Nc + col];
        float w2 = W[(k+2)*Nc + col];
        float w3 = W[(k+3)*Nc + col];
        float4 v;
        v = *(const float4*)&s_s[t0+0][k]; a0 += v.x*w0 + v.y*w1 + v.z*w2 + v.w*w3;
        v = *(const float4*)&s_s[t0+1][k]; a1 += v.x*w0 + v.y*w1 + v.z*w2 + v.w*w3;
        v = *(const float4*)&s_s[t0+2][k]; a2 += v.x*w0 + v.y*w1 + v.z*w2 + v.w*w3;
        v = *(const float4*)&s_s[t0+3][k]; a3 += v.x*w0 + v.y*w1 + v.z*w2 + v.w*w3;
    }
    const float bv = bias[col];
    out[(i0+t0+0)*Nc + col] = a0 + bv;
    out[(i0+t0+1)*Nc + col] = a1 + bv;
    out[(i0+t0+2)*Nc + col] = a2 + bv;
    out[(i0+t0+3)*Nc + col] = a3 + bv;
}

// ---------------- Kernel B: apply rotation+translation to points -----------
__global__ void rotpts_kernel(const float* __restrict__ rot, const float* __restrict__ trans)
{
    const int gid = blockIdx.x*256 + threadIdx.x;
    if (gid >= NTOK*192) return;
    const int i = gid / 192, m = gid % 192;
    const float* R = rot + i*9;
    const float tx = trans[i*3+0], ty = trans[i*3+1], tz = trans[i*3+2];
    float x, y, zc; float* dst;
    if (m < 48) {
        const float* src = g_qpraw + i*144;
        x = src[m]; y = src[48+m]; zc = src[96+m];
        dst = g_qpts + i*144 + m*3;
    } else {
        const int mm = m - 48;
        const float* src = g_kvpraw + i*432;
        x = src[mm]; y = src[144+mm]; zc = src[288+mm];
        const int h = mm / 12, pp = mm % 12;
        if (pp < 4) dst = g_kpts + i*144 + (h*4+pp)*3;
        else        dst = g_vpts + i*288 + (h*8 + pp-4)*3;
    }
    dst[0] = R[0]*x + R[1]*y + R[2]*zc + tx;
    dst[1] = R[3]*x + R[4]*y + R[5]*zc + ty;
    dst[2] = R[6]*x + R[7]*y + R[8]*zc + tz;
}

// ---------------- Kernel C: fused logits + fast softmax ---------------------
// grid 512 (one per query i), block 512 (one thread per key j).
__global__ void __launch_bounds__(512, 3)
attn_kernel(const float* __restrict__ z,
            const float* __restrict__ Wb, const float* __restrict__ bb,
            const float* __restrict__ hwts, const float* __restrict__ mask)
{
    __shared__ float wbT[NH*NCZ];        // Wb transposed [h][c]  6KB
    __shared__ float lgm[NH][NTOK];      // logits matrix         24KB
    __shared__ float qs[NHC];
    __shared__ float qps[NH*NPQ*3];
    __shared__ float sbb[NH];
    __shared__ float shw[NH];
    __shared__ float sinv[NH];

    const int i = blockIdx.x;
    const int tid = threadIdx.x;
    const int j = tid;

    for (int idx = tid; idx < NH*NCZ; idx += 512) {
        const int h = idx >> 7, c = idx & 127;
        wbT[idx] = Wb[c*NH + h];
    }
    if (tid < NHC) qs[tid] = g_qraw[i*NHC + tid];
    else if (tid < NHC + 144) qps[tid-NHC] = g_qpts[i*144 + (tid-NHC)];
    else if (tid < NHC + 144 + NH) {
        const int h = tid - (NHC+144);
        sbb[h] = bb[h];
        shw[h] = log1pf(__expf(hwts[h])) * 0.1360827635f;   // softplus * sqrt(1/54)
    }
    __syncthreads();

    float lg[NH];
    #pragma unroll
    for (int h = 0; h < NH; h++) lg[h] = 0.f;

    // b_pair: z[i,j,:] . Wb[:,h]   (4 z-loads in flight)
    const float4* zr = (const float4*)(z + (size_t)(i*NTOK + j) * NCZ);
    #pragma unroll 4
    for (int cg = 0; cg < 32; cg++) {
        const float4 zv = zr[cg];
        #pragma unroll
        for (int h = 0; h < NH; h++) {
            const float4 wv = *(const float4*)&wbT[h*NCZ + cg*4];
            lg[h] += zv.x*wv.x + zv.y*wv.y + zv.z*wv.z + zv.w*wv.w;
        }
    }

    const float mterm = 100000.0f * (mask[i]*mask[j] - 1.0f);
    const float sc_qk = 0.1443375673f;   // sqrt(1/(3*CH))
    #pragma unroll
    for (int h = 0; h < NH; h++) {
        const float4* kr = (const float4*)(g_kvraw + j*384 + h*32);
        const float4* qr = (const float4*)(qs + h*16);
        float dot = 0.f;
        #pragma unroll
        for (int u = 0; u < 4; u++) {
            const float4 kv = kr[u], qv = qr[u];
            dot += kv.x*qv.x + kv.y*qv.y + kv.z*qv.z + kv.w*qv.w;
        }
        const float4* kpr = (const float4*)(g_kpts + j*144 + h*12);
        const float* qp = qps + h*12;
        const float4 k0 = kpr[0], k1 = kpr[1], k2 = kpr[2];
        float d, dd = 0.f;
        d = qp[0] - k0.x; dd += d*d;
        d = qp[1] - k0.y; dd += d*d;
        d = qp[2] - k0.z; dd += d*d;
        d = qp[3] - k0.w; dd += d*d;
        d = qp[4] - k1.x; dd += d*d;
        d = qp[5] - k1.y; dd += d*d;
        d = qp[6] - k1.z; dd += d*d;
        d = qp[7] - k1.w; dd += d*d;
        d = qp[8] - k2.x; dd += d*d;
        d = qp[9] - k2.y; dd += d*d;
        d = qp[10] - k2.z; dd += d*d;
        d = qp[11] - k2.w; dd += d*d;
        lgm[h][j] = 0.5773502692f*(lg[h] + sbb[h]) + sc_qk*dot - 0.5f*shw[h]*dd + mterm;
    }
    __syncthreads();

    // warp w < 12 does the full softmax reduction for head w
    const int lane = tid & 31, wrp = tid >> 5;
    if (wrp < NH) {
        float m = -3.0e38f;
        #pragma unroll
        for (int t = 0; t < 16; t++)
            m = fmaxf(m, lgm[wrp][t*32 + lane]);
        #pragma unroll
        for (int o = 16; o > 0; o >>= 1)
            m = fmaxf(m, __shfl_xor_sync(0xffffffffu, m, o));
        float su = 0.f;
        #pragma unroll
        for (int t = 0; t < 16; t++) {
            const float e = __expf(lgm[wrp][t*32 + lane] - m);
            lgm[wrp][t*32 + lane] = e;
            su += e;
        }
        #pragma unroll
        for (int o = 16; o > 0; o >>= 1)
            su += __shfl_xor_sync(0xffffffffu, su, o);
        if (lane == 0) sinv[wrp] = 1.0f / su;
    }
    __syncthreads();

    #pragma unroll
    for (int h = 0; h < NH; h++)
        g_attn[h*NNN + i*NTOK + j] = lgm[h][j] * sinv[h];
}

// ---------------- Kernel D: o, o_pt (+inv rot, norms), o_pair --------------
// grid 512 (one per i), block 256.
__global__ void __launch_bounds__(256, 4)
out_kernel(const float* __restrict__ z,
           const float* __restrict__ rot, const float* __restrict__ trans)
{
    __shared__ float a_s[NH*NTOK];   // 24 KB
    __shared__ float p_s[6144];      // 24 KB
    const int i = blockIdx.x;
    const int tid = threadIdx.x;

    for (int idx = tid; idx < NH*NTOK; idx += 256)
        a_s[idx] = g_attn[(idx >> 9)*NNN + i*NTOK + (idx & 511)];
    __syncthreads();

    // o = a@v   and   o_pt = a@v_pts (accumulated in global frame)
    if (tid < 48) {
        const int h = tid >> 2, cg = tid & 3;
        float4 acc = make_float4(0.f,0.f,0.f,0.f);
        const float* base = g_kvraw + h*32 + 16 + cg*4;
        const float* ah = a_s + h*NTOK;
        #pragma unroll 8
        for (int jj = 0; jj < NTOK; jj++) {
            const float4 vv = *(const float4*)(base + jj*384);
            const float a = ah[jj];
            acc.x += a*vv.x; acc.y += a*vv.y; acc.z += a*vv.z; acc.w += a*vv.w;
        }
        *(float4*)&g_cat[i*NOUTD + h*16 + cg*4] = acc;
    } else if (tid < 120) {
        const int m = tid - 48;
        const int h = m / 6, g = m % 6;
        float4 acc = make_float4(0.f,0.f,0.f,0.f);
        const float* base = g_vpts + h*24 + g*4;
        const float* ah = a_s + h*NTOK;
        #pragma unroll 8
        for (int jj = 0; jj < NTOK; jj++) {
            const float4 vv = *(const float4*)(base + jj*288);
            const float a = ah[jj];
            acc.x += a*vv.x; acc.y += a*vv.y; acc.z += a*vv.z; acc.w += a*vv.w;
        }
        *(float4*)&p_s[h*24 + g*4] = acc;
    }
    __syncthreads();

    // inverse rotation, norms
    if (tid < 96) {
        const int h = tid >> 3, p = tid & 7;
        const int m = h*8 + p;
        const float gx = p_s[m*3+0] - trans[i*3+0];
        const float gy = p_s[m*3+1] - trans[i*3+1];
        const float gz = p_s[m*3+2] - trans[i*3+2];
        const float* R = rot + i*9;
        const float lx = R[0]*gx + R[3]*gy + R[6]*gz;
        const float ly = R[1]*gx + R[4]*gy + R[7]*gz;
        const float lz = R[2]*gx + R[5]*gy + R[8]*gz;
        g_cat[i*NOUTD + 192 + m] = lx;
        g_cat[i*NOUTD + 288 + m] = ly;
        g_cat[i*NOUTD + 384 + m] = lz;
        g_cat[i*NOUTD + 480 + m] = sqrtf(lx*lx + ly*ly + lz*lz + 1e-8f);
    }
    __syncthreads();

    // o_pair = a @ z : warp w covers j-quarter (w&3), heads (w>>2)*6..+5.
    const int w = tid >> 5, l = tid & 31;
    const int jq = w & 3;
    const int hbase = (w >> 2) * 6;
    float4 acc[6];
    #pragma unroll
    for (int hh = 0; hh < 6; hh++) acc[hh] = make_float4(0.f,0.f,0.f,0.f);
    const float4* zq = (const float4*)(z + (size_t)(i*NTOK + jq*128)*NCZ) + l;
    #pragma unroll 4
    for (int jj = 0; jj < 128; jj++) {
        const int j = jq*128 + jj;
        const float4 zv = zq[jj*32];
        #pragma unroll
        for (int hh = 0; hh < 6; hh++) {
            const float a = a_s[(hbase+hh)*NTOK + j];
            acc[hh].x += a*zv.x; acc[hh].y += a*zv.y; acc[hh].z += a*zv.z; acc[hh].w += a*zv.w;
        }
    }
    #pragma unroll
    for (int hh = 0; hh < 6; hh++)
        *(float4*)&p_s[w*768 + hh*128 + l*4] = acc[hh];
    __syncthreads();

    for (int o = tid; o < 1536; o += 256) {
        const int h = o >> 7, c = o & 127;
        float sv = 0.f;
        if (h < 6) { for (int ww = 0; ww < 4; ww++) sv += p_s[ww*768 + h*128 + c]; }
        else       { for (int ww = 4; ww < 8; ww++) sv += p_s[ww*768 + (h-6)*128 + c]; }
        g_cat[i*NOUTD + 576 + o] = sv;
    }
}

// ---------------- Kernel E: final GEMM cat(512x2112) @ Wout(2112x384) ------
__global__ void final_gemm(const float* __restrict__ Wout, const float* __restrict__ bout,
                           float* __restrict__ out)
{
    __shared__ float As[32][36];
    __shared__ float Bs[32][36];
    const int bx = blockIdx.x, by = blockIdx.y;
    const int tid = threadIdx.x;
    const int tx = tid & 15, ty = tid >> 4;
    const int lr = tid >> 3, lc = (tid & 7)*4;     // 32 rows x 8 float4
    float c00=0.f, c01=0.f, c10=0.f, c11=0.f;
    for (int kt = 0; kt < NOUTD; kt += 32) {
        *(float4*)&As[lr][lc] = *(const float4*)&g_cat[(by*32 + lr)*NOUTD + kt + lc];
        *(float4*)&Bs[lr][lc] = *(const float4*)&Wout[(kt + lr)*NCS + bx*32 + lc];
        __syncthreads();
        #pragma unroll
        for (int k = 0; k < 32; k++) {
            const float aa0 = As[ty*2+0][k], aa1 = As[ty*2+1][k];
            const float bb0 = Bs[k][tx*2+0], bb1 = Bs[k][tx*2+1];
            c00 += aa0*bb0; c01 += aa0*bb1; c10 += aa1*bb0; c11 += aa1*bb1;
        }
        __syncthreads();
    }
    const int row = by*32 + ty*2, col = bx*32 + tx*2;
    out[row*NCS + col]         = c00 + bout[col];
    out[row*NCS + col+1]       = c01 + bout[col+1];
    out[(row+1)*NCS + col]     = c10 + bout[col];
    out[(row+1)*NCS + col+1]   = c11 + bout[col+1];
}

// ---------------- launch -----------------------------------------------------
extern "C" void kernel_launch(void* const* d_in, const int* in_sizes, int n_in,
                              void* d_out, int out_size)
{
    const float* s     = (const float*)d_in[0];
    const float* z     = (const float*)d_in[1];
    const float* rot   = (const float*)d_in[2];
    const float* trans = (const float*)d_in[3];
    const float* mask  = (const float*)d_in[4];
    const float* Wq    = (const float*)d_in[5];
    const float* bq    = (const float*)d_in[6];
    const float* Wkv   = (const float*)d_in[7];
    const float* bkv   = (const float*)d_in[8];
    const float* Wqp   = (const float*)d_in[9];
    const float* bqp   = (const float*)d_in[10];
    const float* Wkvp  = (const float*)d_in[11];
    const float* bkvp  = (const float*)d_in[12];
    const float* Wb    = (const float*)d_in[13];
    const float* bb    = (const float*)d_in[14];
    const float* hwts  = (const float*)d_in[15];
    const float* Wout  = (const float*)d_in[16];
    const float* bout  = (const float*)d_in[17];
    float* out = (float*)d_out;

    proj_kernel<<<dim3(32,19,1), 256>>>(s, Wq,bq, Wkv,bkv, Wqp,bqp, Wkvp,bkvp);
    rotpts_kernel<<<(NTOK*192 + 255)/256, 256>>>(rot, trans);
    attn_kernel<<<NTOK, 512>>>(z, Wb, bb, hwts, mask);
    out_kernel<<<NTOK, 256>>>(z, rot, trans);
    final_gemm<<<dim3(12,16,1), 256>>>(Wout, bout, out);
}